// round 4
// baseline (speedup 1.0000x reference)
#include <cuda_runtime.h>
#include <math.h>

#define MM 63
#define NN 127
#define BB 256
#define OUT_LOSS (4*BB*NN)
#define MAXC 64          // max row weight (packed, pad idx=127)
#define MAXR 40          // max column weight (packed, pad m=63)
#define NI4  (MAXC/4)
#define NJ4  (MAXR/4)

// g_idx4[i4*512 + job]: 4 packed pre-permuted column indices for job=(t,m), pad=127
// g_cnt4[m]           : ceil(row_weight/4)
// g_rows4[j4*NN + c]  : 4 packed check indices with H[m][c]=1, pad=63 (all NJ4 words padded)
__device__ unsigned g_idx4[NI4 * 512];
__device__ int      g_cnt4[MM];
__device__ unsigned g_rows4[NJ4 * NN];
__device__ float    g_sp;

__global__ __launch_bounds__(1024)
void setup_kernel(const float* __restrict__ H,
                  const float* __restrict__ cw,
                  float* __restrict__ out) {
    __shared__ float sH[MM * NN];
    int tid = threadIdx.x;
    for (int i = tid; i < MM * NN; i += 1024) sH[i] = H[i];
    __syncthreads();

    if (tid < 504) {
        int t = tid / MM, m = tid - t * MM;
        int v = t >> 2, sh = (t & 3) * 31;
        unsigned char cols[MAXC];
        int cnt = 0;
        for (int n = 0; n < NN; ++n)
            if (sH[m * NN + n] != 0.0f && cnt < MAXC) cols[cnt++] = (unsigned char)n;
        if (t == 0) g_cnt4[m] = (cnt + 3) >> 2;
        for (int i4 = 0; i4 < NI4; ++i4) {
            unsigned w = 0;
            for (int k = 0; k < 4; ++k) {
                int i = i4 * 4 + k;
                int idx = NN;  // pad -> s_soft[127] = +huge
                if (i < cnt) {
                    int j = (int)cols[i] - sh; if (j < 0) j += NN;
                    idx = v ? ((2 * j >= NN) ? 2 * j - NN : 2 * j) : j;
                }
                w |= (unsigned)idx << (8 * k);
            }
            g_idx4[i4 * 512 + tid] = w;
        }
    }
    if (tid < NN) {
        int c = tid, rc = 0;
        unsigned char rows[MAXR];
        for (int m = 0; m < MM; ++m)
            if (sH[m * NN + c] != 0.0f && rc < MAXR) rows[rc++] = (unsigned char)m;
        for (int j4 = 0; j4 < NJ4; ++j4) {
            unsigned w = 0;
            for (int k = 0; k < 4; ++k) {
                int j = j4 * 4 + k;
                int mm = (j < rc) ? (int)rows[j] : MM;   // pad -> dummy stats slot 63
                w |= (unsigned)mm << (8 * k);
            }
            g_rows4[j4 * NN + c] = w;
        }
    }
    if (tid == 0) {
        float x = cw[0];
        g_sp = (x > 0.f) ? (x + log1pf(expf(-x))) : log1pf(expf(x));
        out[OUT_LOSS] = 0.0f;
    }
}

__global__ __launch_bounds__(1024)
void decode_kernel(const float* __restrict__ soft_in,
                   const int*   __restrict__ labels,
                   float*       __restrict__ out) {
    __shared__ float  s_soft[NN + 1];      // slot 127 = +huge
    __shared__ float4 s_stats[8 * 64];     // [t][m], m=63 dummy
    __shared__ float  s_red[32];

    const int b   = blockIdx.x;
    const int tid = threadIdx.x;

    // --- staging ---
    for (int n = tid; n < NN; n += 1024) {
        float v = soft_in[b * NN + n];
        s_soft[n] = v;
        out[b * NN + n] = v;                // outs[0]
    }
    if (tid == 0) s_soft[NN] = 1e38f;
    if (tid < 8) s_stats[tid * 64 + MM] = make_float4(-1.f, 0.f, 0.f, 0.f);

    // Phase A identity: lane pair (2j, 2j+1) shares check job j = (t,m)
    const int  jobA   = tid >> 1;
    const int  halfA  = tid & 1;
    const bool validA = (jobA < 504);
    const int  t_a    = validA ? jobA / MM : 0;
    const int  m_a    = validA ? (jobA - t_a * MM) : 0;
    const float coefA = g_sp * ((t_a >> 2) ? 2.0f : 1.0f);
    const int  cnt4   = validA ? g_cnt4[m_a] : 0;   // 0 -> empty loop for invalid lanes

    // Phase B identity: job = (n, t), t = tid&7, n = tid>>3
    const int  t_b    = tid & 7;
    const int  n_b    = tid >> 3;
    const bool validB = (n_b < NN);
    int c_b = 0;
    if (validB) {
        int cb = (t_b >> 2) ? ((n_b * 64) % NN) : n_b;  // inverse permutation
        c_b = cb + (t_b & 3) * 31; if (c_b >= NN) c_b -= NN;
    }
    // Hoist this column's packed check lists into registers (padded with m=63).
    unsigned rw[NJ4];
    #pragma unroll
    for (int j4 = 0; j4 < NJ4; ++j4)
        rw[j4] = validB ? g_rows4[j4 * NN + c_b] : 0x3f3f3f3fu;

    __syncthreads();

    for (int it = 0; it < 3; ++it) {
        // ---------- Phase A: per-check min1/min2/sign (lane-pair split) ----------
        // NOTE: no divergent branch around the warp-sync shuffles — all 32 lanes
        // of every warp execute them (invalid lanes run an empty loop, cnt4==0).
        float m1a = 1e38f, m2a = 1e38f, m1b = 1e38f, m2b = 1e38f;
        unsigned flags = 0u;   // bit31 = sign parity, bit0 = any-zero
        for (int i4 = halfA; i4 < cnt4; i4 += 2) {
            unsigned w = g_idx4[i4 * 512 + jobA];
            float y0 = s_soft[w & 255];
            float y1 = s_soft[(w >> 8) & 255];
            float y2 = s_soft[(w >> 16) & 255];
            float y3 = s_soft[w >> 24];
            flags ^= (__float_as_uint(y0) ^ __float_as_uint(y1) ^
                      __float_as_uint(y2) ^ __float_as_uint(y3)) & 0x80000000u;
            if (y0 == 0.f || y1 == 0.f || y2 == 0.f || y3 == 0.f) flags |= 1u;
            float a0 = fabsf(y0), a1 = fabsf(y1), a2 = fabsf(y2), a3 = fabsf(y3);
            m2a = fminf(m2a, fmaxf(a0, m1a)); m1a = fminf(a0, m1a);
            m2b = fminf(m2b, fmaxf(a1, m1b)); m1b = fminf(a1, m1b);
            m2a = fminf(m2a, fmaxf(a2, m1a)); m1a = fminf(a2, m1a);
            m2b = fminf(m2b, fmaxf(a3, m1b)); m1b = fminf(a3, m1b);
        }
        float min1 = fminf(m1a, m1b);
        float min2 = fminf(fminf(m2a, m2b), fmaxf(m1a, m1b));
        // combine with partner lane (uniform across the whole warp)
        float p1 = __shfl_xor_sync(0xffffffffu, min1, 1);
        float p2 = __shfl_xor_sync(0xffffffffu, min2, 1);
        unsigned pf = __shfl_xor_sync(0xffffffffu, flags, 1);
        min2 = fminf(fminf(min2, p2), fmaxf(min1, p1));
        min1 = fminf(min1, p1);
        unsigned sgbit = (flags ^ pf) & 0x80000000u;
        bool zero = ((flags | pf) & 1u) != 0u;
        if (validA && halfA == 0) {
            float sg = zero ? 0.f : (sgbit ? -1.f : 1.f);
            float cs = coefA * sg;
            s_stats[t_a * 64 + m_a] = make_float4(min1, cs * min1, cs * min2, 0.f);
        }
        __syncthreads();

        // ---------- Phase B: gather per (n, t), reduce over 8 lanes ----------
        float acc = 0.f;
        float y = 0.f;
        if (validB) {
            y = s_soft[n_b];
            float a = fabsf(y);
            float sum0 = 0.f, sum1 = 0.f;
            const float4* st_base = &s_stats[t_b * 64];
            #pragma unroll
            for (int j4 = 0; j4 < NJ4; ++j4) {
                unsigned w = rw[j4];
                float4 s0 = st_base[w & 255];
                float4 s1 = st_base[(w >> 8) & 255];
                float4 s2 = st_base[(w >> 16) & 255];
                float4 s3 = st_base[w >> 24];
                sum0 += (a > s0.x) ? s0.y : s0.z;
                sum1 += (a > s1.x) ? s1.y : s1.z;
                sum0 += (a > s2.x) ? s2.y : s2.z;
                sum1 += (a > s3.x) ? s3.y : s3.z;
            }
            float s1f = (y > 0.f) ? 1.f : ((y < 0.f) ? -1.f : 0.f);
            acc = s1f * (sum0 + sum1);
        }
        acc += __shfl_xor_sync(0xffffffffu, acc, 1);
        acc += __shfl_xor_sync(0xffffffffu, acc, 2);
        acc += __shfl_xor_sync(0xffffffffu, acc, 4);
        if (t_b == 0 && validB) {
            float ns = y + acc * (1.0f / 12.0f);
            s_soft[n_b] = ns;
            out[(it + 1) * BB * NN + b * NN + n_b] = ns;
        }
        __syncthreads();
    }

    // ---------- loss on final soft ----------
    float part = 0.f;
    for (int n = tid; n < NN; n += 1024) {
        float x   = s_soft[n];
        float lf  = (float)labels[b * NN + n];
        float sgn = (x > 0.f) ? 1.f : ((x < 0.f) ? -1.f : 0.f);
        float w   = (sgn != 1.f - 2.f * lf) ? 2.0f : 1.0f;
        float z   = -x;
        float ce  = fmaxf(z, 0.f) - z * lf + log1pf(expf(-fabsf(z)));
        part += w * ce;
    }
    #pragma unroll
    for (int off = 16; off; off >>= 1)
        part += __shfl_down_sync(0xffffffffu, part, off);
    if ((tid & 31) == 0) s_red[tid >> 5] = part;
    __syncthreads();
    if (tid < 32) {
        part = s_red[tid];
        #pragma unroll
        for (int off = 16; off; off >>= 1)
            part += __shfl_down_sync(0xffffffffu, part, off);
        if (tid == 0) atomicAdd(&out[OUT_LOSS], part);
    }
}

extern "C" void kernel_launch(void* const* d_in, const int* in_sizes, int n_in,
                              void* d_out, int out_size) {
    const float* soft = (const float*)d_in[0];
    const int*   lab  = (const int*)d_in[1];
    const float* H    = (const float*)d_in[2];
    const float* cw   = (const float*)d_in[3];
    float* out = (float*)d_out;

    setup_kernel<<<1, 1024>>>(H, cw, out);
    decode_kernel<<<BB, 1024>>>(soft, lab, out);
}

// round 5
// speedup vs baseline: 2.0269x; 2.0269x over previous
#include <cuda_runtime.h>
#include <math.h>

#define MM 63
#define NN 127
#define BB 256
#define OUT_LOSS (4*BB*NN)
#define MAXC 64          // max row weight (packed, pad idx=127)
#define MAXR 40          // max column weight (packed, pad m=63)
#define NI4  (MAXC/4)
#define NJ4  (MAXR/4)

__device__ unsigned g_idx4[NI4 * 512];   // pre-permuted column indices per job=(t,m)
__device__ int      g_cnt4[MM];          // ceil(row_weight/4)
__device__ unsigned g_rows4[NJ4 * NN];   // check indices per column, pad m=63
__device__ int      g_cc4[NN];           // ceil(col_weight/4)
__device__ float    g_sp;

__global__ __launch_bounds__(1024)
void setup_kernel(const float* __restrict__ H,
                  const float* __restrict__ cw,
                  float* __restrict__ out) {
    __shared__ float sH[MM * NN];
    int tid = threadIdx.x;
    for (int i = tid; i < MM * NN; i += 1024) sH[i] = H[i];
    __syncthreads();

    if (tid < 504) {
        int t = tid / MM, m = tid - t * MM;
        int v = t >> 2, sh = (t & 3) * 31;
        unsigned char cols[MAXC];
        int cnt = 0;
        for (int n = 0; n < NN; ++n)
            if (sH[m * NN + n] != 0.0f && cnt < MAXC) cols[cnt++] = (unsigned char)n;
        if (t == 0) g_cnt4[m] = (cnt + 3) >> 2;
        for (int i4 = 0; i4 < NI4; ++i4) {
            unsigned w = 0;
            for (int k = 0; k < 4; ++k) {
                int i = i4 * 4 + k;
                int idx = NN;  // pad -> s_soft[127] = +huge (never the min, sign +)
                if (i < cnt) {
                    int j = (int)cols[i] - sh; if (j < 0) j += NN;
                    idx = v ? ((2 * j >= NN) ? 2 * j - NN : 2 * j) : j;
                }
                w |= (unsigned)idx << (8 * k);
            }
            g_idx4[i4 * 512 + tid] = w;
        }
    }
    if (tid < NN) {
        int c = tid, rc = 0;
        unsigned char rows[MAXR];
        for (int m = 0; m < MM; ++m)
            if (sH[m * NN + c] != 0.0f && rc < MAXR) rows[rc++] = (unsigned char)m;
        g_cc4[c] = (rc + 3) >> 2;
        for (int j4 = 0; j4 < NJ4; ++j4) {
            unsigned w = 0;
            for (int k = 0; k < 4; ++k) {
                int j = j4 * 4 + k;
                int mm = (j < rc) ? (int)rows[j] : MM;   // pad -> b1 slot 63 == 0
                w |= (unsigned)mm << (8 * k);
            }
            g_rows4[j4 * NN + c] = w;
        }
    }
    if (tid == 0) {
        float x = cw[0];
        g_sp = (x > 0.f) ? (x + log1pf(expf(-x))) : log1pf(expf(x));
        out[OUT_LOSS] = 0.0f;
    }
}

__global__ __launch_bounds__(1024)
void decode_kernel(const float* __restrict__ soft_in,
                   const int*   __restrict__ labels,
                   float*       __restrict__ out) {
    __shared__ float    s_soft[2][NN + 1];   // slot 127 = +huge
    __shared__ float    s_b1[2][8 * 64];     // [row][t*64+m], m=63 => 0
    __shared__ float    s_corr[2][NN];       // argmin corrections
    __shared__ unsigned s_rows4[NJ4 * NN];
    __shared__ int      s_cc4[NN];
    __shared__ float    s_red[32];

    const int tid  = threadIdx.x;
    const int row  = tid >> 9;
    const int rtid = tid & 511;
    const int b    = blockIdx.x * 2 + row;

    // --- staging ---
    if (rtid < NN) {
        float v = soft_in[b * NN + rtid];
        s_soft[row][rtid] = v;
        out[b * NN + rtid] = v;               // outs[0]
        s_corr[row][rtid] = 0.f;
    }
    if (rtid == NN) s_soft[row][NN] = 1e38f;
    if (rtid < 8)   s_b1[row][rtid * 64 + 63] = 0.f;   // pad slot
    for (int i = tid; i < NJ4 * NN; i += 1024) s_rows4[i] = g_rows4[i];
    for (int i = tid; i < NN; i += 1024)       s_cc4[i] = g_cc4[i];

    // Phase A identity: one check job per thread (no warp shuffles in Phase A)
    const bool validA = (rtid < 504);
    const int  t_a    = validA ? rtid / MM : 0;
    const int  m_a    = validA ? (rtid - t_a * MM) : 0;
    const float coefA = g_sp * ((t_a >> 2) ? 2.0f : 1.0f);
    const int  cnt4   = validA ? g_cnt4[m_a] : 0;

    // Phase B identity: t = rtid&7, n in {n0, n0+64}
    const int t_b = rtid & 7;
    const int n0  = rtid >> 3;
    int  cB[2]; bool vB[2];
    #pragma unroll
    for (int r = 0; r < 2; ++r) {
        int n = n0 + 64 * r;
        vB[r] = (n < NN);
        int cb = (t_b >> 2) ? ((n * 64) % NN) : n;     // inverse permutation
        int c  = cb + (t_b & 3) * 31; if (c >= NN) c -= NN;
        cB[r] = vB[r] ? c : 0;
    }

    __syncthreads();

    for (int it = 0; it < 3; ++it) {
        // ---------- Phase A: per-check min1/min2/sign + argmin scatter ----------
        if (validA) {
            const float* ss = s_soft[row];
            float m1a = 1e38f, m2a = 1e38f, m1b = 1e38f, m2b = 1e38f;
            int   ia = 0, ib = 0;
            unsigned sx = 0u; bool zz = false;
            #pragma unroll 2
            for (int i4 = 0; i4 < cnt4; ++i4) {
                unsigned w = g_idx4[i4 * 512 + rtid];
                int i0 = w & 255, i1 = (w >> 8) & 255, i2 = (w >> 16) & 255, i3 = w >> 24;
                float y0 = ss[i0], y1 = ss[i1], y2 = ss[i2], y3 = ss[i3];
                sx ^= (__float_as_uint(y0) ^ __float_as_uint(y1) ^
                       __float_as_uint(y2) ^ __float_as_uint(y3)) & 0x80000000u;
                zz |= (y0 == 0.f) | (y1 == 0.f) | (y2 == 0.f) | (y3 == 0.f);
                float a0 = fabsf(y0), a1 = fabsf(y1), a2 = fabsf(y2), a3 = fabsf(y3);
                if (a0 < m1a) { m2a = m1a; m1a = a0; ia = i0; } else m2a = fminf(m2a, a0);
                if (a1 < m1b) { m2b = m1b; m1b = a1; ib = i1; } else m2b = fminf(m2b, a1);
                if (a2 < m1a) { m2a = m1a; m1a = a2; ia = i2; } else m2a = fminf(m2a, a2);
                if (a3 < m1b) { m2b = m1b; m1b = a3; ib = i3; } else m2b = fminf(m2b, a3);
            }
            float min1, min2; int im;
            if (m1a <= m1b) { min1 = m1a; im = ia; min2 = fminf(m1b, m2a); }
            else            { min1 = m1b; im = ib; min2 = fminf(m1a, m2b); }
            float sg = zz ? 0.f : (sx ? -1.f : 1.f);
            float cs = coefA * sg;
            s_b1[row][t_a * 64 + m_a] = cs * min1;
            float ym = ss[im];
            float s1 = (ym > 0.f) ? 1.f : ((ym < 0.f) ? -1.f : 0.f);
            atomicAdd(&s_corr[row][im], s1 * cs * (min2 - min1));
        }
        __syncthreads();

        // ---------- Phase B: scalar b1 gather per (n,t), 8-lane reduce ----------
        float acc[2], yv[2];
        const float* bt = &s_b1[row][t_b * 64];
        #pragma unroll
        for (int r = 0; r < 2; ++r) {
            float a = 0.f; yv[r] = 0.f;
            if (vB[r]) {
                int c  = cB[r];
                int cc = s_cc4[c];
                float sum = 0.f;
                for (int j4 = 0; j4 < cc; ++j4) {
                    unsigned w = s_rows4[j4 * NN + c];
                    sum += bt[w & 255] + bt[(w >> 8) & 255]
                         + bt[(w >> 16) & 255] + bt[w >> 24];
                }
                float y = s_soft[row][n0 + 64 * r];
                yv[r] = y;
                float s1 = (y > 0.f) ? 1.f : ((y < 0.f) ? -1.f : 0.f);
                a = s1 * sum;
            }
            acc[r] = a;
        }
        #pragma unroll
        for (int r = 0; r < 2; ++r) {
            acc[r] += __shfl_xor_sync(0xffffffffu, acc[r], 1);
            acc[r] += __shfl_xor_sync(0xffffffffu, acc[r], 2);
            acc[r] += __shfl_xor_sync(0xffffffffu, acc[r], 4);
        }
        if (t_b == 0) {
            #pragma unroll
            for (int r = 0; r < 2; ++r) {
                if (vB[r]) {
                    int n = n0 + 64 * r;
                    float cr = s_corr[row][n];
                    s_corr[row][n] = 0.f;   // self-zero for next iteration
                    float ns = yv[r] + (acc[r] + cr) * (1.0f / 12.0f);
                    s_soft[row][n] = ns;
                    out[(it + 1) * BB * NN + b * NN + n] = ns;
                }
            }
        }
        __syncthreads();
    }

    // ---------- loss on final soft ----------
    float part = 0.f;
    if (rtid < NN) {
        float x   = s_soft[row][rtid];
        float lf  = (float)labels[b * NN + rtid];
        float sgn = (x > 0.f) ? 1.f : ((x < 0.f) ? -1.f : 0.f);
        float w   = (sgn != 1.f - 2.f * lf) ? 2.0f : 1.0f;
        float z   = -x;
        part = w * (fmaxf(z, 0.f) - z * lf + log1pf(expf(-fabsf(z))));
    }
    #pragma unroll
    for (int off = 16; off; off >>= 1)
        part += __shfl_down_sync(0xffffffffu, part, off);
    if ((tid & 31) == 0) s_red[tid >> 5] = part;
    __syncthreads();
    if (tid < 32) {
        part = s_red[tid];
        #pragma unroll
        for (int off = 16; off; off >>= 1)
            part += __shfl_down_sync(0xffffffffu, part, off);
        if (tid == 0) atomicAdd(&out[OUT_LOSS], part);
    }
}

extern "C" void kernel_launch(void* const* d_in, const int* in_sizes, int n_in,
                              void* d_out, int out_size) {
    const float* soft = (const float*)d_in[0];
    const int*   lab  = (const int*)d_in[1];
    const float* H    = (const float*)d_in[2];
    const float* cw   = (const float*)d_in[3];
    float* out = (float*)d_out;

    setup_kernel<<<1, 1024>>>(H, cw, out);
    decode_kernel<<<BB / 2, 1024>>>(soft, lab, out);
}

// round 6
// speedup vs baseline: 2.2646x; 1.1173x over previous
#include <cuda_runtime.h>
#include <math.h>

#define MM 63
#define NN 127
#define BB 256
#define OUT_LOSS (4*BB*NN)
#define MAXC 64
#define MAXR 40
#define NI4  (MAXC/4)
#define NJ4  (MAXR/4)

__device__ unsigned g_idx4[NI4 * 512];   // pre-permuted column indices per job=(t,m), pad=127
__device__ int      g_cnt4[MM];          // ceil(row_weight/4)
__device__ unsigned g_rows4[NJ4 * NN];   // check indices per column, pad m=63
__device__ int      g_cc4[NN];           // ceil(col_weight/4)
__device__ float    g_sp;

__global__ __launch_bounds__(1024)
void setup_kernel(const float* __restrict__ H,
                  const float* __restrict__ cw,
                  float* __restrict__ out) {
    __shared__ float sH[MM * NN];
    __shared__ unsigned char s_cols[MM][MAXC];
    __shared__ int s_cnt[MM];
    int tid = threadIdx.x;
    for (int i = tid; i < MM * NN; i += 1024) sH[i] = H[i];
    __syncthreads();

    // Row col-lists (shared-resident, no local arrays).
    if (tid < MM) {
        int m = tid, cnt = 0;
        for (int n = 0; n < NN; ++n)
            if (sH[m * NN + n] != 0.0f && cnt < MAXC) s_cols[m][cnt++] = (unsigned char)n;
        s_cnt[m] = cnt;
        g_cnt4[m] = (cnt + 3) >> 2;
    }
    // Column check-lists, packed on the fly in registers.
    if (tid >= 512 && tid < 512 + NN) {
        int c = tid - 512, rc = 0, j4 = 0;
        unsigned w = 0;
        for (int m = 0; m < MM; ++m) {
            if (sH[m * NN + c] != 0.0f) {
                w |= (unsigned)m << (8 * (rc & 3));
                if ((++rc & 3) == 0) { if (j4 < NJ4) g_rows4[j4 * NN + c] = w; ++j4; w = 0; }
            }
        }
        g_cc4[c] = (rc + 3) >> 2;
        if (rc & 3) {                      // pad last word with m=63 (b1 slot == 0)
            for (int k = rc & 3; k < 4; ++k) w |= 63u << (8 * k);
            if (j4 < NJ4) g_rows4[j4 * NN + c] = w;
        }
    }
    __syncthreads();

    // 504 jobs: apply sigma_t to the shared col list.
    if (tid < 504) {
        int t = tid / MM, m = tid - t * MM;
        int v = t >> 2, sh = (t & 3) * 31;
        int cnt = s_cnt[m];
        int n4 = (cnt + 3) >> 2;
        for (int i4 = 0; i4 < n4; ++i4) {
            unsigned w = 0;
            for (int k = 0; k < 4; ++k) {
                int i = i4 * 4 + k;
                int idx = NN;  // pad -> s_soft[127] = +huge
                if (i < cnt) {
                    int j = (int)s_cols[m][i] - sh; if (j < 0) j += NN;
                    idx = v ? ((2 * j >= NN) ? 2 * j - NN : 2 * j) : j;
                }
                w |= (unsigned)idx << (8 * k);
            }
            g_idx4[i4 * 512 + tid] = w;
        }
    }
    if (tid == 0) {
        float x = cw[0];
        g_sp = (x > 0.f) ? (x + log1pf(expf(-x))) : log1pf(expf(x));
        out[OUT_LOSS] = 0.0f;
    }
}

__global__ __launch_bounds__(1024)
void decode_kernel(const float* __restrict__ soft_in,
                   const int*   __restrict__ labels,
                   float*       __restrict__ out) {
    __shared__ float    s_soft[2][NN + 1];   // slot 127 = +huge
    __shared__ float    s_b1[2][8 * 64];     // [row][t*64+m], m=63 => 0
    __shared__ float    s_corr[2][NN];
    __shared__ unsigned s_rows4[NJ4 * NN];
    __shared__ float    s_red[32];

    const int tid  = threadIdx.x;
    const int row  = tid >> 9;
    const int rtid = tid & 511;
    const int b    = blockIdx.x * 2 + row;

    if (rtid < NN) {
        float v = soft_in[b * NN + rtid];
        s_soft[row][rtid] = v;
        out[b * NN + rtid] = v;               // outs[0]
        s_corr[row][rtid] = 0.f;
    }
    if (rtid == NN) s_soft[row][NN] = 1e38f;
    if (rtid < 8)   s_b1[row][rtid * 64 + 63] = 0.f;
    for (int i = tid; i < NJ4 * NN; i += 1024) s_rows4[i] = g_rows4[i];

    // Phase A identity
    const bool validA = (rtid < 504);
    const int  t_a    = validA ? rtid / MM : 0;
    const int  m_a    = validA ? (rtid - t_a * MM) : 0;
    const float coefA = g_sp * ((t_a >> 2) ? 2.0f : 1.0f);
    const int  cnt4   = validA ? g_cnt4[m_a] : 0;

    // Phase B identity: t = rtid&7, n in {n0, n0+64}
    const int t_b = rtid & 7;
    const int n0  = rtid >> 3;
    int cB[2]; bool vB[2]; int ccB[2];
    #pragma unroll
    for (int r = 0; r < 2; ++r) {
        int n = n0 + 64 * r;
        vB[r] = (n < NN);
        int cb = (t_b >> 2) ? ((n * 64) % NN) : n;
        int c  = cb + (t_b & 3) * 31; if (c >= NN) c -= NN;
        cB[r]  = vB[r] ? c : 0;
        ccB[r] = vB[r] ? g_cc4[c] : 0;
    }

    __syncthreads();

    for (int it = 0; it < 3; ++it) {
        // ---------- Phase A: uint-key top-2 + argmin + sign parity ----------
        if (validA) {
            const unsigned* us = (const unsigned*)s_soft[row];
            unsigned k1a = ~0u, k2a = ~0u, k1b = ~0u, k2b = ~0u, sx = 0u;
            #pragma unroll 2
            for (int i4 = 0; i4 < cnt4; ++i4) {
                unsigned w = g_idx4[i4 * 512 + rtid];
                int i0 = w & 255, i1 = (w >> 8) & 255, i2 = (w >> 16) & 255, i3 = w >> 24;
                unsigned u0 = us[i0], u1 = us[i1], u2 = us[i2], u3 = us[i3];
                sx ^= u0 ^ u1 ^ u2 ^ u3;
                unsigned key0 = (u0 & 0x7FFFFF80u) | (unsigned)i0;
                unsigned key1 = (u1 & 0x7FFFFF80u) | (unsigned)i1;
                unsigned key2 = (u2 & 0x7FFFFF80u) | (unsigned)i2;
                unsigned key3 = (u3 & 0x7FFFFF80u) | (unsigned)i3;
                k2a = min(k2a, max(key0, k1a)); k1a = min(k1a, key0);
                k2b = min(k2b, max(key1, k1b)); k1b = min(k1b, key1);
                k2a = min(k2a, max(key2, k1a)); k1a = min(k1a, key2);
                k2b = min(k2b, max(key3, k1b)); k1b = min(k1b, key3);
            }
            unsigned k1 = min(k1a, k1b);
            unsigned k2 = min(min(k2a, k2b), max(k1a, k1b));
            unsigned a1 = k1 & 0x7FFFFF80u;
            float min1 = __uint_as_float(a1);
            float min2 = __uint_as_float(k2 & 0x7FFFFF80u);
            int   im   = (int)(k1 & 127u);
            float sg   = a1 ? ((sx & 0x80000000u) ? -1.f : 1.f) : 0.f;
            float cs   = coefA * sg;
            s_b1[row][t_a * 64 + m_a] = cs * min1;
            float ym = s_soft[row][im];
            float s1 = (ym > 0.f) ? 1.f : ((ym < 0.f) ? -1.f : 0.f);
            atomicAdd(&s_corr[row][im], s1 * cs * (min2 - min1));
        }
        __syncthreads();

        // ---------- Phase B: scalar b1 gather per (n,t), 8-lane reduce ----------
        float acc[2], yv[2];
        const float* bt = &s_b1[row][t_b * 64];
        #pragma unroll
        for (int r = 0; r < 2; ++r) {
            float a = 0.f; yv[r] = 0.f;
            if (vB[r]) {
                int c = cB[r];
                float sum = 0.f;
                for (int j4 = 0; j4 < ccB[r]; ++j4) {
                    unsigned w = s_rows4[j4 * NN + c];
                    sum += bt[w & 255] + bt[(w >> 8) & 255]
                         + bt[(w >> 16) & 255] + bt[w >> 24];
                }
                float y = s_soft[row][n0 + 64 * r];
                yv[r] = y;
                float s1 = (y > 0.f) ? 1.f : ((y < 0.f) ? -1.f : 0.f);
                a = s1 * sum;
            }
            acc[r] = a;
        }
        #pragma unroll
        for (int r = 0; r < 2; ++r) {
            acc[r] += __shfl_xor_sync(0xffffffffu, acc[r], 1);
            acc[r] += __shfl_xor_sync(0xffffffffu, acc[r], 2);
            acc[r] += __shfl_xor_sync(0xffffffffu, acc[r], 4);
        }
        if (t_b == 0) {
            #pragma unroll
            for (int r = 0; r < 2; ++r) {
                if (vB[r]) {
                    int n = n0 + 64 * r;
                    float cr = s_corr[row][n];
                    s_corr[row][n] = 0.f;
                    float ns = yv[r] + (acc[r] + cr) * (1.0f / 12.0f);
                    s_soft[row][n] = ns;
                    out[(it + 1) * BB * NN + b * NN + n] = ns;
                }
            }
        }
        __syncthreads();
    }

    // ---------- loss ----------
    float part = 0.f;
    if (rtid < NN) {
        float x   = s_soft[row][rtid];
        float lf  = (float)labels[b * NN + rtid];
        float sgn = (x > 0.f) ? 1.f : ((x < 0.f) ? -1.f : 0.f);
        float w   = (sgn != 1.f - 2.f * lf) ? 2.0f : 1.0f;
        float z   = -x;
        part = w * (fmaxf(z, 0.f) - z * lf + log1pf(expf(-fabsf(z))));
    }
    #pragma unroll
    for (int off = 16; off; off >>= 1)
        part += __shfl_down_sync(0xffffffffu, part, off);
    if ((tid & 31) == 0) s_red[tid >> 5] = part;
    __syncthreads();
    if (tid < 32) {
        part = s_red[tid];
        #pragma unroll
        for (int off = 16; off; off >>= 1)
            part += __shfl_down_sync(0xffffffffu, part, off);
        if (tid == 0) atomicAdd(&out[OUT_LOSS], part);
    }
}

extern "C" void kernel_launch(void* const* d_in, const int* in_sizes, int n_in,
                              void* d_out, int out_size) {
    const float* soft = (const float*)d_in[0];
    const int*   lab  = (const int*)d_in[1];
    const float* H    = (const float*)d_in[2];
    const float* cw   = (const float*)d_in[3];
    float* out = (float*)d_out;

    setup_kernel<<<1, 1024>>>(H, cw, out);
    decode_kernel<<<BB / 2, 1024>>>(soft, lab, out);
}

// round 7
// speedup vs baseline: 2.4257x; 1.0712x over previous
#include <cuda_runtime.h>
#include <math.h>

#define MM 63
#define NN 127
#define BB 256
#define OUT_LOSS (4*BB*NN)
#define NI4 16            // capacity: packed col words per check row (pad c=127)
#define NJ4 10            // capacity: packed check words per column (pad m=63)

__device__ unsigned g_cols4[NI4 * 64];   // [i4*64+m] raw H column indices, pad 127
__device__ int      g_cnt4[MM];          // ceil(row_weight/4)
__device__ unsigned g_rows4[NJ4 * NN];   // [j4*127+c] check indices, pad 63
__device__ int      g_cc4[NN];           // ceil(col_weight/4)
__device__ float    g_sp;

__global__ __launch_bounds__(1024)
void setup_kernel(const float* __restrict__ H,
                  const float* __restrict__ cw,
                  float* __restrict__ out) {
    __shared__ float sH[MM * NN];
    int tid = threadIdx.x;
    for (int i = tid; i < MM * NN; i += 1024) sH[i] = H[i];
    __syncthreads();

    if (tid < MM) {                       // row col-lists, packed in registers
        int m = tid, cnt = 0, i4 = 0;
        unsigned w = 0;
        for (int n = 0; n < NN; ++n) {
            if (sH[m * NN + n] != 0.0f) {
                w |= (unsigned)n << (8 * (cnt & 3));
                if ((++cnt & 3) == 0) { if (i4 < NI4) g_cols4[i4 * 64 + m] = w; ++i4; w = 0; }
            }
        }
        g_cnt4[m] = (cnt + 3) >> 2;
        if (cnt & 3) {
            for (int k = cnt & 3; k < 4; ++k) w |= 127u << (8 * k);
            if (i4 < NI4) g_cols4[i4 * 64 + m] = w;
        }
    }
    if (tid >= 128 && tid < 128 + NN) {   // column check-lists
        int c = tid - 128, rc = 0, j4 = 0;
        unsigned w = 0;
        for (int m = 0; m < MM; ++m) {
            if (sH[m * NN + c] != 0.0f) {
                w |= (unsigned)m << (8 * (rc & 3));
                if ((++rc & 3) == 0) { if (j4 < NJ4) g_rows4[j4 * NN + c] = w; ++j4; w = 0; }
            }
        }
        g_cc4[c] = (rc + 3) >> 2;
        if (rc & 3) {
            for (int k = rc & 3; k < 4; ++k) w |= 63u << (8 * k);
            if (j4 < NJ4) g_rows4[j4 * NN + c] = w;
        }
    }
    if (tid == 0) {
        float x = cw[0];
        g_sp = (x > 0.f) ? (x + log1pf(expf(-x))) : log1pf(expf(x));
        out[OUT_LOSS] = 0.0f;
    }
}

__device__ __forceinline__ int sigma_apply(int c, int sh, int v) {
    int j = c - sh; if (j < 0) j += NN;
    return v ? ((2 * j >= NN) ? 2 * j - NN : 2 * j) : j;
}

__global__ __launch_bounds__(1024)
void decode_kernel(const float* __restrict__ soft_in,
                   const int*   __restrict__ labels,
                   float*       __restrict__ out) {
    __shared__ float    s_soft[2][NN + 1];
    __shared__ float    s_rot[2][128 * 8];   // [c*8+t], c=127 slots = +huge
    __shared__ float    s_b1R[2][64 * 8];    // [m*8+t], m=63 slots = 0
    __shared__ float    s_corr[2][NN + 1];
    __shared__ unsigned s_rows4[NJ4 * NN];
    __shared__ unsigned s_cols4[NI4 * 64];
    __shared__ float    s_red[32];

    const int tid  = threadIdx.x;
    const int row  = tid >> 9;
    const int rtid = tid & 511;
    const int b    = blockIdx.x * 2 + row;

    // --- staging ---
    if (rtid < NN) {
        float v = soft_in[b * NN + rtid];
        s_soft[row][rtid] = v;
        out[b * NN + rtid] = v;               // outs[0]
        s_corr[row][rtid] = 0.f;
    }
    if (rtid == NN) s_soft[row][NN] = 1e38f;
    if (rtid < 8)   s_b1R[row][63 * 8 + rtid] = 0.f;
    s_cols4[tid] = g_cols4[tid];              // exactly 1024 words
    for (int i = tid; i < NJ4 * NN; i += 1024) s_rows4[i] = g_rows4[i];

    // rot-build identities (2 jobs/thread): j = rtid, rtid+512
    int sig0 = -1, sig1 = -1;
    {
        int j = rtid, c = j >> 3, t = j & 7;
        if (c < NN) sig0 = sigma_apply(c, (t & 3) * 31, t >> 2);
        j = rtid + 512; c = j >> 3; t = j & 7;
        if (c < NN) sig1 = sigma_apply(c, (t & 3) * 31, t >> 2);
    }

    // Phase A identity: m = rtid>>3, t = rtid&7
    const int  m_a    = rtid >> 3;
    const int  t_a    = rtid & 7;
    const bool validA = (m_a < MM);
    const int  vA     = t_a >> 2;
    const int  shA    = (t_a & 3) * 31;
    const float coefA = g_sp * (vA ? 2.0f : 1.0f);
    const int  cntA   = validA ? g_cnt4[m_a] : 0;

    // Phase B identity: t = rtid&7, n in {n0, n0+64}
    const int t_b = rtid & 7;
    const int n0  = rtid >> 3;
    int cB[2]; bool vB[2]; int ccB[2];
    #pragma unroll
    for (int r = 0; r < 2; ++r) {
        int n = n0 + 64 * r;
        vB[r] = (n < NN);
        int cb = (t_b >> 2) ? ((n * 64) % NN) : n;
        int c  = cb + (t_b & 3) * 31; if (c >= NN) c -= NN;
        cB[r]  = vB[r] ? c : 0;
        ccB[r] = vB[r] ? g_cc4[c] : 0;
    }

    __syncthreads();

    for (int it = 0; it < 3; ++it) {
        // ---------- rot build: rot[c*8+t] = soft[sigma_t(c)] ----------
        s_rot[row][rtid]       = (sig0 < 0) ? 1e38f : s_soft[row][sig0];
        s_rot[row][rtid + 512] = (sig1 < 0) ? 1e38f : s_soft[row][sig1];
        __syncthreads();

        // ---------- Phase A: per-check top-2 + argmin + parity ----------
        if (validA) {
            const unsigned* rt = (const unsigned*)&s_rot[row][t_a];
            unsigned k1a = ~0u, k2a = ~0u, k1b = ~0u, k2b = ~0u, sx = 0u;
            for (int i4 = 0; i4 < cntA; ++i4) {
                unsigned w = s_cols4[i4 * 64 + m_a];   // broadcast across 8 lanes
                int c0 = w & 255, c1 = (w >> 8) & 255, c2 = (w >> 16) & 255, c3 = w >> 24;
                unsigned u0 = rt[c0 * 8], u1 = rt[c1 * 8], u2 = rt[c2 * 8], u3 = rt[c3 * 8];
                sx ^= u0 ^ u1 ^ u2 ^ u3;
                unsigned key0 = (u0 & 0x7FFFFF80u) | (unsigned)c0;
                unsigned key1 = (u1 & 0x7FFFFF80u) | (unsigned)c1;
                unsigned key2 = (u2 & 0x7FFFFF80u) | (unsigned)c2;
                unsigned key3 = (u3 & 0x7FFFFF80u) | (unsigned)c3;
                k2a = min(k2a, max(key0, k1a)); k1a = min(k1a, key0);
                k2b = min(k2b, max(key1, k1b)); k1b = min(k1b, key1);
                k2a = min(k2a, max(key2, k1a)); k1a = min(k1a, key2);
                k2b = min(k2b, max(key3, k1b)); k1b = min(k1b, key3);
            }
            unsigned k1 = min(k1a, k1b);
            unsigned k2 = min(min(k2a, k2b), max(k1a, k1b));
            unsigned a1 = k1 & 0x7FFFFF80u;
            float min1 = __uint_as_float(a1);
            float min2 = __uint_as_float(k2 & 0x7FFFFF80u);
            int   cmin = (int)(k1 & 127u);
            float sg   = a1 ? ((sx & 0x80000000u) ? -1.f : 1.f) : 0.f;
            float cs   = coefA * sg;
            s_b1R[row][m_a * 8 + t_a] = cs * min1;
            float ym = s_rot[row][cmin * 8 + t_a];
            float s1 = (ym > 0.f) ? 1.f : ((ym < 0.f) ? -1.f : 0.f);
            int  nstar = sigma_apply(cmin, shA, vA);
            atomicAdd(&s_corr[row][nstar], s1 * cs * (min2 - min1));
        }
        __syncthreads();

        // ---------- Phase B: gather b1R per (n,t), 8-lane reduce ----------
        float acc[2], yv[2];
        const float* bt = &s_b1R[row][t_b];
        #pragma unroll
        for (int r = 0; r < 2; ++r) {
            float a = 0.f; yv[r] = 0.f;
            if (vB[r]) {
                int c = cB[r];
                float sum = 0.f;
                for (int j4 = 0; j4 < ccB[r]; ++j4) {
                    unsigned w = s_rows4[j4 * NN + c];
                    sum += bt[(w & 255) * 8] + bt[((w >> 8) & 255) * 8]
                         + bt[((w >> 16) & 255) * 8] + bt[(w >> 24) * 8];
                }
                float y = s_soft[row][n0 + 64 * r];
                yv[r] = y;
                float s1 = (y > 0.f) ? 1.f : ((y < 0.f) ? -1.f : 0.f);
                a = s1 * sum;
            }
            acc[r] = a;
        }
        #pragma unroll
        for (int r = 0; r < 2; ++r) {
            acc[r] += __shfl_xor_sync(0xffffffffu, acc[r], 1);
            acc[r] += __shfl_xor_sync(0xffffffffu, acc[r], 2);
            acc[r] += __shfl_xor_sync(0xffffffffu, acc[r], 4);
        }
        if (t_b == 0) {
            #pragma unroll
            for (int r = 0; r < 2; ++r) {
                if (vB[r]) {
                    int n = n0 + 64 * r;
                    float cr = s_corr[row][n];
                    s_corr[row][n] = 0.f;
                    float ns = yv[r] + (acc[r] + cr) * (1.0f / 12.0f);
                    s_soft[row][n] = ns;
                    out[(it + 1) * BB * NN + b * NN + n] = ns;
                }
            }
        }
        __syncthreads();
    }

    // ---------- loss ----------
    float part = 0.f;
    if (rtid < NN) {
        float x   = s_soft[row][rtid];
        float lf  = (float)labels[b * NN + rtid];
        float sgn = (x > 0.f) ? 1.f : ((x < 0.f) ? -1.f : 0.f);
        float w   = (sgn != 1.f - 2.f * lf) ? 2.0f : 1.0f;
        float z   = -x;
        part = w * (fmaxf(z, 0.f) - z * lf + log1pf(expf(-fabsf(z))));
    }
    #pragma unroll
    for (int off = 16; off; off >>= 1)
        part += __shfl_down_sync(0xffffffffu, part, off);
    if ((tid & 31) == 0) s_red[tid >> 5] = part;
    __syncthreads();
    if (tid < 32) {
        part = s_red[tid];
        #pragma unroll
        for (int off = 16; off; off >>= 1)
            part += __shfl_down_sync(0xffffffffu, part, off);
        if (tid == 0) atomicAdd(&out[OUT_LOSS], part);
    }
}

extern "C" void kernel_launch(void* const* d_in, const int* in_sizes, int n_in,
                              void* d_out, int out_size) {
    const float* soft = (const float*)d_in[0];
    const int*   lab  = (const int*)d_in[1];
    const float* H    = (const float*)d_in[2];
    const float* cw   = (const float*)d_in[3];
    float* out = (float*)d_out;

    setup_kernel<<<1, 1024>>>(H, cw, out);
    decode_kernel<<<BB / 2, 1024>>>(soft, lab, out);
}